// round 8
// baseline (speedup 1.0000x reference)
#include <cuda_runtime.h>

#define N_SRC   100000
#define N_DST   50000
#define N_EDGES 800000

// Scratch (static device arrays — no allocation)
__device__ int                g_row_ptr[N_DST + 1];
__device__ unsigned long long g_w1p[64 * 64];   // (w,w) pairs, W[:, 0:64],  k-major
__device__ unsigned long long g_w2p[64 * 64];   // (w,w) pairs, W[:, 64:128], k-major

__device__ __forceinline__ unsigned long long pack2(float v) {
    unsigned long long r;
    asm("mov.b64 %0, {%1, %1};" : "=l"(r) : "f"(v));
    return r;
}
__device__ __forceinline__ void fma2(unsigned long long& d, unsigned long long a,
                                     unsigned long long b) {
    asm("fma.rn.f32x2 %0, %1, %2, %0;" : "+l"(d) : "l"(a), "l"(b));
}

// ---------------------------------------------------------------------------
// Prep A: build row_ptr from the sorted dst_idx.
// ---------------------------------------------------------------------------
__global__ void build_row_ptr_kernel(const int* __restrict__ dst_idx) {
    int e = blockIdx.x * blockDim.x + threadIdx.x;
    if (e >= N_EDGES) return;
    int d = dst_idx[e];
    int dprev = (e == 0) ? -1 : dst_idx[e - 1];
    for (int x = dprev + 1; x <= d; ++x) g_row_ptr[x] = e;
    if (e == N_EDGES - 1) {
        for (int x = d + 1; x <= N_DST; ++x) g_row_ptr[x] = N_EDGES;
    }
}

// ---------------------------------------------------------------------------
// Prep B: transpose + pair-pack W [64][128] into g_w1p/g_w2p (k-major).
// ---------------------------------------------------------------------------
__global__ void prep_w_kernel(const float* __restrict__ W) {
    int t = blockIdx.x * blockDim.x + threadIdx.x;   // 0..8191
    if (t >= 64 * 128) return;
    int o = t >> 7;          // 0..63
    int k = t & 127;         // 0..127
    float v = W[o * 128 + k];
    if (k < 64) g_w1p[k * 64 + o] = pack2(v);
    else        g_w2p[(k - 64) * 64 + o] = pack2(v);
}

// ---------------------------------------------------------------------------
// Kernel 1 (block-specialized):
//  blocks [0, AGG_BLOCKS): aggregation + CV blend -> out_hn  (L2-bound)
//  blocks [AGG_BLOCKS, +GEMM_BLOCKS): partial = H_dst @ W1^T  (fma-bound)
// The two bottlenecks overlap on-chip in one launch.
// ---------------------------------------------------------------------------
#define AGG_ROWS    8
#define AGG_BLOCKS  ((N_DST + AGG_ROWS - 1) / AGG_ROWS)          // 6250
#define G_ROWS      64
#define GEMM_BLOCKS ((N_DST + G_ROWS - 1) / G_ROWS)              // 782
#define K1_THREADS  256

__device__ __forceinline__ void gemm_half(
    const float* __restrict__ X,          // [N_DST, 64] input half
    const unsigned long long* __restrict__ wp,  // packed W half, k-major
    const float* __restrict__ bias,       // nullptr for pass 1
    const float* __restrict__ partial,    // nullptr for pass 1
    float* __restrict__ out,
    int rowBase, float* xt /* [64][64] smem */)
{
    const int tid = threadIdx.x;

    // stage X tile k-major with swizzle r ^ (k & 56)
    for (int i = tid; i < 64 * 16; i += K1_THREADS) {
        int r  = i >> 4;
        int c4 = i & 15;
        int row = rowBase + r;
        float4 v = make_float4(0.f, 0.f, 0.f, 0.f);
        if (row < N_DST) v = ((const float4*)X)[row * 16 + c4];
        int k0 = 4 * c4;
        xt[(k0 + 0) * 64 + (r ^ ((k0 + 0) & 56))] = v.x;
        xt[(k0 + 1) * 64 + (r ^ ((k0 + 1) & 56))] = v.y;
        xt[(k0 + 2) * 64 + (r ^ ((k0 + 2) & 56))] = v.z;
        xt[(k0 + 3) * 64 + (r ^ ((k0 + 3) & 56))] = v.w;
    }
    __syncthreads();

    const int rg = tid >> 4;     // 0..15 -> rows 4*rg .. 4*rg+3
    const int cg = tid & 15;     // 0..15 -> outs 4*cg .. 4*cg+3

    unsigned long long acc[2][4];
#pragma unroll
    for (int p = 0; p < 2; p++)
#pragma unroll
        for (int j = 0; j < 4; j++) acc[p][j] = 0ULL;

    const ulonglong2* wp2 = (const ulonglong2*)wp;

#pragma unroll 8
    for (int k = 0; k < 64; k++) {
        const int sw = k & 56;
        float4 xq = *(const float4*)&xt[k * 64 + ((4 * rg) ^ sw)];
        unsigned long long xv0, xv1;
        asm("mov.b64 %0, {%1, %2};" : "=l"(xv0) : "f"(xq.x), "f"(xq.y));
        asm("mov.b64 %0, {%1, %2};" : "=l"(xv1) : "f"(xq.z), "f"(xq.w));

        // pre-packed (w,w) pairs: outs 4cg..4cg+3 = two 16B loads
        ulonglong2 wa = __ldg(&wp2[k * 32 + 2 * cg]);
        ulonglong2 wb = __ldg(&wp2[k * 32 + 2 * cg + 1]);

        fma2(acc[0][0], xv0, wa.x);
        fma2(acc[0][1], xv0, wa.y);
        fma2(acc[0][2], xv0, wb.x);
        fma2(acc[0][3], xv0, wb.y);
        fma2(acc[1][0], xv1, wa.x);
        fma2(acc[1][1], xv1, wa.y);
        fma2(acc[1][2], xv1, wb.x);
        fma2(acc[1][3], xv1, wb.y);
    }

    const bool finalize = (bias != nullptr);
    float4 bv = make_float4(0.f, 0.f, 0.f, 0.f);
    if (finalize) bv = __ldg(&((const float4*)bias)[cg]);

#pragma unroll
    for (int p = 0; p < 2; p++) {
        float lo[4], hi[4];
#pragma unroll
        for (int j = 0; j < 4; j++) {
            float l, h;
            asm("mov.b64 {%0, %1}, %2;" : "=f"(l), "=f"(h) : "l"(acc[p][j]));
            lo[j] = l; hi[j] = h;
        }
        int r0 = rowBase + 4 * rg + 2 * p;
#pragma unroll
        for (int q = 0; q < 2; q++) {
            int row = r0 + q;
            if (row >= N_DST) continue;
            const float* s = q ? hi : lo;
            float4 v;
            if (finalize) {
                float4 pv = ((const float4*)partial)[row * 16 + cg];
                v.x = fmaxf(s[0] + pv.x + bv.x, 0.f);
                v.y = fmaxf(s[1] + pv.y + bv.y, 0.f);
                v.z = fmaxf(s[2] + pv.z + bv.z, 0.f);
                v.w = fmaxf(s[3] + pv.w + bv.w, 0.f);
            } else {
                v.x = s[0]; v.y = s[1]; v.z = s[2]; v.w = s[3];
            }
            ((float4*)out)[row * 16 + cg] = v;
        }
    }
}

__global__ __launch_bounds__(K1_THREADS, 4) void fused_agg_gemm1_kernel(
    const float* __restrict__ H_src,
    const float* __restrict__ H_dst,
    const float* __restrict__ HBar,
    const int*   __restrict__ src_idx,
    float* __restrict__ out_hn,
    float* __restrict__ out_h)      // partial (no bias/relu yet)
{
    __shared__ float xt[64 * 64];   // 16KB, gemm path only

    if (blockIdx.x >= AGG_BLOCKS) {
        // ---- GEMM pass 1: partial = H_dst @ W1^T ----
        int rowBase = (blockIdx.x - AGG_BLOCKS) * G_ROWS;
        gemm_half(H_dst, g_w1p, nullptr, nullptr, out_h, rowBase, xt);
        return;
    }

    // ---- aggregation + CV blend ----
    const int warp = threadIdx.x >> 5;
    const int lane = threadIdx.x & 31;
    const int row  = blockIdx.x * AGG_ROWS + warp;
    if (row >= N_DST) return;

    const int start = g_row_ptr[row];
    const int end   = g_row_ptr[row + 1];
    const int deg   = end - start;

    const float2* Hs2 = (const float2*)H_src;
    float2 hb = ((const float2*)HBar)[row * 32 + lane];

    float2 sum = make_float2(0.f, 0.f);
    int e = start;
    for (; e + 7 < end; e += 8) {
        int s0 = src_idx[e + 0], s1 = src_idx[e + 1];
        int s2 = src_idx[e + 2], s3 = src_idx[e + 3];
        int s4 = src_idx[e + 4], s5 = src_idx[e + 5];
        int s6 = src_idx[e + 6], s7 = src_idx[e + 7];
        float2 a0 = Hs2[s0 * 32 + lane];
        float2 a1 = Hs2[s1 * 32 + lane];
        float2 a2 = Hs2[s2 * 32 + lane];
        float2 a3 = Hs2[s3 * 32 + lane];
        float2 a4 = Hs2[s4 * 32 + lane];
        float2 a5 = Hs2[s5 * 32 + lane];
        float2 a6 = Hs2[s6 * 32 + lane];
        float2 a7 = Hs2[s7 * 32 + lane];
        sum.x += ((a0.x + a1.x) + (a2.x + a3.x)) + ((a4.x + a5.x) + (a6.x + a7.x));
        sum.y += ((a0.y + a1.y) + (a2.y + a3.y)) + ((a4.y + a5.y) + (a6.y + a7.y));
    }
    for (; e + 1 < end; e += 2) {
        int s0 = src_idx[e + 0], s1 = src_idx[e + 1];
        float2 a0 = Hs2[s0 * 32 + lane];
        float2 a1 = Hs2[s1 * 32 + lane];
        sum.x += a0.x + a1.x;
        sum.y += a0.y + a1.y;
    }
    if (e < end) {
        int s = src_idx[e];
        float2 a = Hs2[s * 32 + lane];
        sum.x += a.x;
        sum.y += a.y;
    }

    float inv = 1.0f / (float)max(deg, 1);
    float2 hn;
    hn.x = 0.9f * hb.x + 0.1f * (sum.x * inv);
    hn.y = 0.9f * hb.y + 0.1f * (sum.y * inv);
    ((float2*)out_hn)[row * 32 + lane] = hn;
}

// ---------------------------------------------------------------------------
// Kernel 2: out_h = relu(partial + hn @ W2^T + bias)
// ---------------------------------------------------------------------------
__global__ __launch_bounds__(K1_THREADS, 4) void gemm2_kernel(
    const float* __restrict__ hn,
    const float* __restrict__ bias,
    float* __restrict__ out_h)
{
    __shared__ float xt[64 * 64];
    int rowBase = blockIdx.x * G_ROWS;
    gemm_half(hn, g_w2p, bias, out_h, out_h, rowBase, xt);
}

// ---------------------------------------------------------------------------
extern "C" void kernel_launch(void* const* d_in, const int* in_sizes, int n_in,
                              void* d_out, int out_size) {
    const float* H_src   = (const float*)d_in[0];
    const float* H_dst   = (const float*)d_in[1];
    const float* HBar    = (const float*)d_in[2];
    const int*   src_idx = (const int*)  d_in[3];
    const int*   dst_idx = (const int*)  d_in[4];
    const float* W       = (const float*)d_in[5];
    const float* bias    = (const float*)d_in[6];

    float* out_h  = (float*)d_out;                     // [N_DST, 64]
    float* out_hn = (float*)d_out + N_DST * 64;        // [N_DST, 64]

    build_row_ptr_kernel<<<(N_EDGES + 255) / 256, 256>>>(dst_idx);
    prep_w_kernel<<<(64 * 128 + 255) / 256, 256>>>(W);

    // Overlapped: aggregation (L2-bound) + H_dst half-GEMM (fma-bound)
    fused_agg_gemm1_kernel<<<AGG_BLOCKS + GEMM_BLOCKS, K1_THREADS>>>(
        H_src, H_dst, HBar, src_idx, out_hn, out_h);

    // Finalize: += hn @ W2^T, + bias, relu
    gemm2_kernel<<<GEMM_BLOCKS, K1_THREADS>>>(out_hn, bias, out_h);
}

// round 9
// speedup vs baseline: 1.4565x; 1.4565x over previous
#include <cuda_runtime.h>

#define N_SRC   100000
#define N_DST   50000
#define N_EDGES 800000

// Scratch (static device arrays — no allocation)
__device__ int   g_row_ptr[N_DST + 1];
__device__ float g_w1t[64 * 64];   // W[:, 0:64]^T  : w1t[k][o], k-major
__device__ float g_w2t[64 * 64];   // W[:, 64:128]^T: w2t[k][o], k-major

__device__ __forceinline__ unsigned long long pack2(float v) {
    unsigned long long r;
    asm("mov.b64 %0, {%1, %1};" : "=l"(r) : "f"(v));
    return r;
}
__device__ __forceinline__ void fma2(unsigned long long& d, unsigned long long a,
                                     unsigned long long b) {
    asm("fma.rn.f32x2 %0, %1, %2, %0;" : "+l"(d) : "l"(a), "l"(b));
}

// ---------------------------------------------------------------------------
// Prep A: build row_ptr from the sorted dst_idx.
// ---------------------------------------------------------------------------
__global__ void build_row_ptr_kernel(const int* __restrict__ dst_idx) {
    int e = blockIdx.x * blockDim.x + threadIdx.x;
    if (e >= N_EDGES) return;
    int d = dst_idx[e];
    int dprev = (e == 0) ? -1 : dst_idx[e - 1];
    for (int x = dprev + 1; x <= d; ++x) g_row_ptr[x] = e;
    if (e == N_EDGES - 1) {
        for (int x = d + 1; x <= N_DST; ++x) g_row_ptr[x] = N_EDGES;
    }
}

// ---------------------------------------------------------------------------
// Prep B: transpose W [64][128] into two k-major halves (plain float).
// ---------------------------------------------------------------------------
__global__ void prep_w_kernel(const float* __restrict__ W) {
    int t = blockIdx.x * blockDim.x + threadIdx.x;   // 0..8191
    if (t >= 64 * 128) return;
    int o = t >> 7;          // 0..63
    int k = t & 127;         // 0..127
    float v = W[o * 128 + k];
    if (k < 64) g_w1t[k * 64 + o] = v;
    else        g_w2t[(k - 64) * 64 + o] = v;
}

// ---------------------------------------------------------------------------
// Shared GEMM core: out = X[128 rows] @ Whalf^T (K=64), optional finalize.
// 256 threads; thread tile 8 rows x 4 outs; f32x2 FMAs.
// xt[k][r]: k-major, [64][128] floats, 32KB. No swizzle needed:
//   stage stores: lanes -> consecutive r  => banks 0..31, conflict-free
//   main reads  : 2 distinct 16B addrs/warp, aligned, conflict-free
// ---------------------------------------------------------------------------
#define GR_ROWS     128
#define GEMM_BLOCKS ((N_DST + GR_ROWS - 1) / GR_ROWS)   // 391
#define THREADS     256

__device__ __forceinline__ void gemm_pass(
    const float* __restrict__ X,        // [N_DST, 64]
    const float* __restrict__ wt,       // [64][64] k-major half of W
    const float* __restrict__ partial,  // nullptr => pass 1 (plain store)
    const float* __restrict__ bias,     // nullptr => pass 1
    float* __restrict__ out,
    int rowBase, float* xt)
{
    const int tid = threadIdx.x;

    // --- stage X tile k-major: i -> (r = i&127, c4 = i>>7) ---
    // lanes map to consecutive rows => smem stores hit all 32 banks.
    for (int i = tid; i < GR_ROWS * 16; i += THREADS) {
        int r  = i & 127;
        int c4 = i >> 7;
        int row = rowBase + r;
        float4 v = make_float4(0.f, 0.f, 0.f, 0.f);
        if (row < N_DST) v = ((const float4*)X)[row * 16 + c4];
        int k0 = 4 * c4;
        xt[(k0 + 0) * 128 + r] = v.x;
        xt[(k0 + 1) * 128 + r] = v.y;
        xt[(k0 + 2) * 128 + r] = v.z;
        xt[(k0 + 3) * 128 + r] = v.w;
    }
    __syncthreads();

    const int rg = tid >> 4;    // 0..15 -> rows 8*rg .. 8*rg+7
    const int cg = tid & 15;    // 0..15 -> outs 4*cg .. 4*cg+3

    unsigned long long acc[4][4];
#pragma unroll
    for (int p = 0; p < 4; p++)
#pragma unroll
        for (int j = 0; j < 4; j++) acc[p][j] = 0ULL;

    const float4* wt4 = (const float4*)wt;

#pragma unroll 8
    for (int k = 0; k < 64; k++) {
        // 8 rows of x as 4 packed pairs: two aligned 16B LDS
        ulonglong2 xlo = *(const ulonglong2*)&xt[k * 128 + 8 * rg];
        ulonglong2 xhi = *(const ulonglong2*)&xt[k * 128 + 8 * rg + 4];

        float4 wv = __ldg(&wt4[k * 16 + cg]);   // contiguous across warp: 2 wf
        unsigned long long w0 = pack2(wv.x);
        unsigned long long w1 = pack2(wv.y);
        unsigned long long w2 = pack2(wv.z);
        unsigned long long w3 = pack2(wv.w);

        fma2(acc[0][0], xlo.x, w0); fma2(acc[0][1], xlo.x, w1);
        fma2(acc[0][2], xlo.x, w2); fma2(acc[0][3], xlo.x, w3);
        fma2(acc[1][0], xlo.y, w0); fma2(acc[1][1], xlo.y, w1);
        fma2(acc[1][2], xlo.y, w2); fma2(acc[1][3], xlo.y, w3);
        fma2(acc[2][0], xhi.x, w0); fma2(acc[2][1], xhi.x, w1);
        fma2(acc[2][2], xhi.x, w2); fma2(acc[2][3], xhi.x, w3);
        fma2(acc[3][0], xhi.y, w0); fma2(acc[3][1], xhi.y, w1);
        fma2(acc[3][2], xhi.y, w2); fma2(acc[3][3], xhi.y, w3);
    }

    const bool finalize = (bias != nullptr);
    float4 bv = make_float4(0.f, 0.f, 0.f, 0.f);
    if (finalize) bv = __ldg(&((const float4*)bias)[cg]);

#pragma unroll
    for (int p = 0; p < 4; p++) {
        float lo[4], hi[4];
#pragma unroll
        for (int j = 0; j < 4; j++) {
            float l, h;
            asm("mov.b64 {%0, %1}, %2;" : "=f"(l), "=f"(h) : "l"(acc[p][j]));
            lo[j] = l; hi[j] = h;
        }
        int r0 = rowBase + 8 * rg + 2 * p;
#pragma unroll
        for (int q = 0; q < 2; q++) {
            int row = r0 + q;
            if (row >= N_DST) continue;
            const float* s = q ? hi : lo;
            float4 v;
            if (finalize) {
                float4 pv = ((const float4*)partial)[row * 16 + cg];
                v.x = fmaxf(s[0] + pv.x + bv.x, 0.f);
                v.y = fmaxf(s[1] + pv.y + bv.y, 0.f);
                v.z = fmaxf(s[2] + pv.z + bv.z, 0.f);
                v.w = fmaxf(s[3] + pv.w + bv.w, 0.f);
            } else {
                v.x = s[0]; v.y = s[1]; v.z = s[2]; v.w = s[3];
            }
            ((float4*)out)[row * 16 + cg] = v;
        }
    }
}

// ---------------------------------------------------------------------------
// Kernel 1: interleaved agg (L2-bound) + gemm1 = H_dst @ W1^T (issue-bound).
// Every 17th block ID is a gemm block -> both populations co-resident on
// every SM for the duration of the launch (true overlap).
// ---------------------------------------------------------------------------
#define AGG_ROWS   8
#define AGG_BLOCKS ((N_DST + AGG_ROWS - 1) / AGG_ROWS)   // 6250
#define K1_GRID    (AGG_BLOCKS + GEMM_BLOCKS)            // 6641
#define STRIDE     17

__global__ __launch_bounds__(THREADS, 4) void fused_agg_gemm1_kernel(
    const float* __restrict__ H_src,
    const float* __restrict__ H_dst,
    const float* __restrict__ HBar,
    const int*   __restrict__ src_idx,
    float* __restrict__ out_hn,
    float* __restrict__ out_h)     // partial (no bias/relu yet)
{
    __shared__ float xt[64 * 128];  // 32KB, gemm path only

    const int bid = blockIdx.x;
    const bool is_gemm = (bid % STRIDE == 0) && (bid / STRIDE < GEMM_BLOCKS);

    if (is_gemm) {
        int rowBase = (bid / STRIDE) * GR_ROWS;
        gemm_pass(H_dst, g_w1t, nullptr, nullptr, out_h, rowBase, xt);
        return;
    }

    // agg_id = bid minus number of gemm blocks with smaller/equal id
    int gemm_before = min(bid / STRIDE + 1, GEMM_BLOCKS);
    int agg_id = bid - gemm_before;

    const int warp = threadIdx.x >> 5;
    const int lane = threadIdx.x & 31;
    const int row  = agg_id * AGG_ROWS + warp;
    if (row >= N_DST) return;

    const int start = g_row_ptr[row];
    const int end   = g_row_ptr[row + 1];
    const int deg   = end - start;

    const float2* Hs2 = (const float2*)H_src;
    float2 hb = ((const float2*)HBar)[row * 32 + lane];

    float2 sum = make_float2(0.f, 0.f);
    int e = start;
    for (; e + 7 < end; e += 8) {
        int s0 = src_idx[e + 0], s1 = src_idx[e + 1];
        int s2 = src_idx[e + 2], s3 = src_idx[e + 3];
        int s4 = src_idx[e + 4], s5 = src_idx[e + 5];
        int s6 = src_idx[e + 6], s7 = src_idx[e + 7];
        float2 a0 = Hs2[s0 * 32 + lane];
        float2 a1 = Hs2[s1 * 32 + lane];
        float2 a2 = Hs2[s2 * 32 + lane];
        float2 a3 = Hs2[s3 * 32 + lane];
        float2 a4 = Hs2[s4 * 32 + lane];
        float2 a5 = Hs2[s5 * 32 + lane];
        float2 a6 = Hs2[s6 * 32 + lane];
        float2 a7 = Hs2[s7 * 32 + lane];
        sum.x += ((a0.x + a1.x) + (a2.x + a3.x)) + ((a4.x + a5.x) + (a6.x + a7.x));
        sum.y += ((a0.y + a1.y) + (a2.y + a3.y)) + ((a4.y + a5.y) + (a6.y + a7.y));
    }
    for (; e + 1 < end; e += 2) {
        int s0 = src_idx[e + 0], s1 = src_idx[e + 1];
        float2 a0 = Hs2[s0 * 32 + lane];
        float2 a1 = Hs2[s1 * 32 + lane];
        sum.x += a0.x + a1.x;
        sum.y += a0.y + a1.y;
    }
    if (e < end) {
        int s = src_idx[e];
        float2 a = Hs2[s * 32 + lane];
        sum.x += a.x;
        sum.y += a.y;
    }

    float inv = 1.0f / (float)max(deg, 1);
    float2 hn;
    hn.x = 0.9f * hb.x + 0.1f * (sum.x * inv);
    hn.y = 0.9f * hb.y + 0.1f * (sum.y * inv);
    ((float2*)out_hn)[row * 32 + lane] = hn;
}

// ---------------------------------------------------------------------------
// Kernel 2: out_h = relu(partial + hn @ W2^T + bias)
// ---------------------------------------------------------------------------
__global__ __launch_bounds__(THREADS, 4) void gemm2_kernel(
    const float* __restrict__ hn,
    const float* __restrict__ bias,
    float* __restrict__ out_h)
{
    __shared__ float xt[64 * 128];
    int rowBase = blockIdx.x * GR_ROWS;
    gemm_pass(hn, g_w2t, out_h, bias, out_h, rowBase, xt);
}

// ---------------------------------------------------------------------------
extern "C" void kernel_launch(void* const* d_in, const int* in_sizes, int n_in,
                              void* d_out, int out_size) {
    const float* H_src   = (const float*)d_in[0];
    const float* H_dst   = (const float*)d_in[1];
    const float* HBar    = (const float*)d_in[2];
    const int*   src_idx = (const int*)  d_in[3];
    const int*   dst_idx = (const int*)  d_in[4];
    const float* W       = (const float*)d_in[5];
    const float* bias    = (const float*)d_in[6];

    float* out_h  = (float*)d_out;                     // [N_DST, 64]
    float* out_hn = (float*)d_out + N_DST * 64;        // [N_DST, 64]

    build_row_ptr_kernel<<<(N_EDGES + 255) / 256, 256>>>(dst_idx);
    prep_w_kernel<<<(64 * 128 + 255) / 256, 256>>>(W);

    // Overlapped: aggregation (L2-bound) + H_dst half-GEMM (issue-bound)
    fused_agg_gemm1_kernel<<<K1_GRID, THREADS>>>(
        H_src, H_dst, HBar, src_idx, out_hn, out_h);

    // Finalize: += hn @ W2^T, + bias, relu
    gemm2_kernel<<<GEMM_BLOCKS, THREADS>>>(out_hn, bias, out_h);
}

// round 10
// speedup vs baseline: 1.9604x; 1.3459x over previous
#include <cuda_runtime.h>

#define N_SRC   100000
#define N_DST   50000
#define N_EDGES 800000

// Scratch (static device arrays — no allocation)
__device__ int   g_row_ptr[N_DST + 1];
__device__ float g_wt[128 * 64];   // W^T: wt[k][o], k-major, full K=128

__device__ __forceinline__ unsigned long long pack2(float v) {
    unsigned long long r;
    asm("mov.b64 %0, {%1, %1};" : "=l"(r) : "f"(v));
    return r;
}
__device__ __forceinline__ void fma2(unsigned long long& d, unsigned long long a,
                                     unsigned long long b) {
    asm("fma.rn.f32x2 %0, %1, %2, %0;" : "+l"(d) : "l"(a), "l"(b));
}

// ---------------------------------------------------------------------------
// Prep (merged): blocks [0, EDGE_BLOCKS) build row_ptr from sorted dst_idx;
// blocks [EDGE_BLOCKS, +W_BLOCKS) transpose W [64][128] -> g_wt[k][o].
// ---------------------------------------------------------------------------
#define EDGE_BLOCKS ((N_EDGES + 255) / 256)      // 3125
#define W_BLOCKS    ((64 * 128 + 255) / 256)     // 32

__global__ void prep_kernel(const int* __restrict__ dst_idx,
                            const float* __restrict__ W) {
    if (blockIdx.x >= EDGE_BLOCKS) {
        int t = (blockIdx.x - EDGE_BLOCKS) * blockDim.x + threadIdx.x;
        if (t < 64 * 128) {
            int o = t >> 7;          // 0..63
            int k = t & 127;         // 0..127
            g_wt[k * 64 + o] = W[o * 128 + k];
        }
        return;
    }
    int e = blockIdx.x * blockDim.x + threadIdx.x;
    if (e >= N_EDGES) return;
    int d = dst_idx[e];
    int dprev = (e == 0) ? -1 : dst_idx[e - 1];
    for (int x = dprev + 1; x <= d; ++x) g_row_ptr[x] = e;
    if (e == N_EDGES - 1) {
        for (int x = d + 1; x <= N_DST; ++x) g_row_ptr[x] = N_EDGES;
    }
}

// ---------------------------------------------------------------------------
// Kernel B: aggregation + CV blend. Warp per dst row, 8-way unrolled gather.
// No smem -> max occupancy. Writes h_neigh only. (R6-proven, ~near L2 floor.)
// ---------------------------------------------------------------------------
#define AGG_THREADS 256
#define AGG_ROWS    8

__global__ __launch_bounds__(AGG_THREADS) void aggregate_kernel(
    const float* __restrict__ H_src,
    const float* __restrict__ HBar,
    const int*   __restrict__ src_idx,
    float* __restrict__ out_hn)
{
    const int warp = threadIdx.x >> 5;
    const int lane = threadIdx.x & 31;
    const int row  = blockIdx.x * AGG_ROWS + warp;
    if (row >= N_DST) return;

    const int start = g_row_ptr[row];
    const int end   = g_row_ptr[row + 1];
    const int deg   = end - start;

    const float2* Hs2 = (const float2*)H_src;
    float2 hb = ((const float2*)HBar)[row * 32 + lane];

    float2 sum = make_float2(0.f, 0.f);
    int e = start;
    for (; e + 7 < end; e += 8) {
        int s0 = src_idx[e + 0], s1 = src_idx[e + 1];
        int s2 = src_idx[e + 2], s3 = src_idx[e + 3];
        int s4 = src_idx[e + 4], s5 = src_idx[e + 5];
        int s6 = src_idx[e + 6], s7 = src_idx[e + 7];
        float2 a0 = Hs2[s0 * 32 + lane];
        float2 a1 = Hs2[s1 * 32 + lane];
        float2 a2 = Hs2[s2 * 32 + lane];
        float2 a3 = Hs2[s3 * 32 + lane];
        float2 a4 = Hs2[s4 * 32 + lane];
        float2 a5 = Hs2[s5 * 32 + lane];
        float2 a6 = Hs2[s6 * 32 + lane];
        float2 a7 = Hs2[s7 * 32 + lane];
        sum.x += ((a0.x + a1.x) + (a2.x + a3.x)) + ((a4.x + a5.x) + (a6.x + a7.x));
        sum.y += ((a0.y + a1.y) + (a2.y + a3.y)) + ((a4.y + a5.y) + (a6.y + a7.y));
    }
    for (; e + 1 < end; e += 2) {
        int s0 = src_idx[e + 0], s1 = src_idx[e + 1];
        float2 a0 = Hs2[s0 * 32 + lane];
        float2 a1 = Hs2[s1 * 32 + lane];
        sum.x += a0.x + a1.x;
        sum.y += a0.y + a1.y;
    }
    if (e < end) {
        int s = src_idx[e];
        float2 a = Hs2[s * 32 + lane];
        sum.x += a.x;
        sum.y += a.y;
    }

    float inv = 1.0f / (float)max(deg, 1);
    float2 hn;
    hn.x = 0.9f * hb.x + 0.1f * (sum.x * inv);
    hn.y = 0.9f * hb.y + 0.1f * (sum.y * inv);
    ((float2*)out_hn)[row * 32 + lane] = hn;
}

// ---------------------------------------------------------------------------
// Kernel C: GEMM  h = relu([H_dst | h_neigh] @ W^T + b)
// 64 rows x 64 outs per 128-thread block, full K=128.
// Thread tile: 8 rows x 4 outs. Per k: 2 LDS.128 + 1 LDG.128 (W, L1-hot)
// + 4 packs + 16 fma.rn.f32x2  => 23 inst / 32 FMA.
// X k-major in 32KB smem, swizzle r ^ (k & 56):
//   reading positions (8rg)^sw + j (j=0..7) yields rows 8rg+j in order,
//   since +j touches only bits 0-2 and ^sw flips bits 3-5 back.
// ---------------------------------------------------------------------------
#define G_ROWS    64
#define G_THREADS 128
#define GEMM_BLOCKS ((N_DST + G_ROWS - 1) / G_ROWS)   // 782

__global__ __launch_bounds__(G_THREADS, 6) void gemm_kernel(
    const float* __restrict__ H_dst,
    const float* __restrict__ hn,
    const float* __restrict__ bias,
    float* __restrict__ out_h)
{
    __shared__ float xt[128][64];   // 32KB

    const int tid = threadIdx.x;
    const int rowBase = blockIdx.x * G_ROWS;

    // --- stage X: k<64 from H_dst, k>=64 from hn; coalesced global reads,
    //     swizzled conflict-free smem stores ---
    for (int i = tid; i < 64 * 16; i += G_THREADS) {
        int r  = i >> 4;
        int c4 = i & 15;
        int row = rowBase + r;
        float4 vd = make_float4(0.f, 0.f, 0.f, 0.f);
        float4 vn = make_float4(0.f, 0.f, 0.f, 0.f);
        if (row < N_DST) {
            vd = ((const float4*)H_dst)[row * 16 + c4];
            vn = ((const float4*)hn)   [row * 16 + c4];
        }
        int k0 = 4 * c4;
        xt[k0 + 0][r ^ ((k0 + 0) & 56)] = vd.x;
        xt[k0 + 1][r ^ ((k0 + 1) & 56)] = vd.y;
        xt[k0 + 2][r ^ ((k0 + 2) & 56)] = vd.z;
        xt[k0 + 3][r ^ ((k0 + 3) & 56)] = vd.w;
        int k1 = 64 + 4 * c4;
        xt[k1 + 0][r ^ ((k1 + 0) & 56)] = vn.x;
        xt[k1 + 1][r ^ ((k1 + 1) & 56)] = vn.y;
        xt[k1 + 2][r ^ ((k1 + 2) & 56)] = vn.z;
        xt[k1 + 3][r ^ ((k1 + 3) & 56)] = vn.w;
    }
    __syncthreads();

    // --- mainloop: 8 rows (4 packed pairs) x 4 outs per thread ---
    const int rg = tid >> 4;    // 0..7  -> rows 8*rg .. 8*rg+7
    const int cg = tid & 15;    // 0..15 -> outs 4*cg .. 4*cg+3

    unsigned long long acc[4][4];
#pragma unroll
    for (int p = 0; p < 4; p++)
#pragma unroll
        for (int j = 0; j < 4; j++) acc[p][j] = 0ULL;

    const float4* wt4 = (const float4*)g_wt;

#pragma unroll 8
    for (int k = 0; k < 128; k++) {
        const int sw = k & 56;
        const int base = (8 * rg) ^ sw;           // 8-aligned
        ulonglong2 xlo = *(const ulonglong2*)&xt[k][base];      // rows 8rg..+3
        ulonglong2 xhi = *(const ulonglong2*)&xt[k][base + 4];  // rows 8rg+4..+7

        float4 wv = __ldg(&wt4[k * 16 + cg]);     // 256B contiguous per warp
        unsigned long long w0 = pack2(wv.x);
        unsigned long long w1 = pack2(wv.y);
        unsigned long long w2 = pack2(wv.z);
        unsigned long long w3 = pack2(wv.w);

        fma2(acc[0][0], xlo.x, w0); fma2(acc[0][1], xlo.x, w1);
        fma2(acc[0][2], xlo.x, w2); fma2(acc[0][3], xlo.x, w3);
        fma2(acc[1][0], xlo.y, w0); fma2(acc[1][1], xlo.y, w1);
        fma2(acc[1][2], xlo.y, w2); fma2(acc[1][3], xlo.y, w3);
        fma2(acc[2][0], xhi.x, w0); fma2(acc[2][1], xhi.x, w1);
        fma2(acc[2][2], xhi.x, w2); fma2(acc[2][3], xhi.x, w3);
        fma2(acc[3][0], xhi.y, w0); fma2(acc[3][1], xhi.y, w1);
        fma2(acc[3][2], xhi.y, w2); fma2(acc[3][3], xhi.y, w3);
    }

    // --- epilogue: bias + relu, float4 stores ---
    float4 bv = __ldg(&((const float4*)bias)[cg]);
#pragma unroll
    for (int p = 0; p < 4; p++) {
        float lo[4], hi[4];
#pragma unroll
        for (int j = 0; j < 4; j++) {
            float l, h;
            asm("mov.b64 {%0, %1}, %2;" : "=f"(l), "=f"(h) : "l"(acc[p][j]));
            lo[j] = l; hi[j] = h;
        }
        int r0 = rowBase + 8 * rg + 2 * p;
        if (r0 < N_DST) {
            float4 v;
            v.x = fmaxf(lo[0] + bv.x, 0.f);
            v.y = fmaxf(lo[1] + bv.y, 0.f);
            v.z = fmaxf(lo[2] + bv.z, 0.f);
            v.w = fmaxf(lo[3] + bv.w, 0.f);
            ((float4*)out_h)[r0 * 16 + cg] = v;
        }
        if (r0 + 1 < N_DST) {
            float4 v;
            v.x = fmaxf(hi[0] + bv.x, 0.f);
            v.y = fmaxf(hi[1] + bv.y, 0.f);
            v.z = fmaxf(hi[2] + bv.z, 0.f);
            v.w = fmaxf(hi[3] + bv.w, 0.f);
            ((float4*)out_h)[(r0 + 1) * 16 + cg] = v;
        }
    }
}

// ---------------------------------------------------------------------------
extern "C" void kernel_launch(void* const* d_in, const int* in_sizes, int n_in,
                              void* d_out, int out_size) {
    const float* H_src   = (const float*)d_in[0];
    const float* H_dst   = (const float*)d_in[1];
    const float* HBar    = (const float*)d_in[2];
    const int*   src_idx = (const int*)  d_in[3];
    const int*   dst_idx = (const int*)  d_in[4];
    const float* W       = (const float*)d_in[5];
    const float* bias    = (const float*)d_in[6];

    float* out_h  = (float*)d_out;                     // [N_DST, 64]
    float* out_hn = (float*)d_out + N_DST * 64;        // [N_DST, 64]

    prep_kernel<<<EDGE_BLOCKS + W_BLOCKS, 256>>>(dst_idx, W);

    aggregate_kernel<<<(N_DST + AGG_ROWS - 1) / AGG_ROWS, AGG_THREADS>>>(
        H_src, HBar, src_idx, out_hn);

    gemm_kernel<<<GEMM_BLOCKS, G_THREADS>>>(H_dst, out_hn, bias, out_h);
}

// round 11
// speedup vs baseline: 2.0136x; 1.0271x over previous
#include <cuda_runtime.h>

#define N_SRC   100000
#define N_DST   50000
#define N_EDGES 800000

// Scratch (static device arrays — no allocation)
__device__ int   g_row_ptr[N_DST + 1];
__device__ float g_wt[128 * 64];   // W^T: wt[k][o], k-major, full K=128

__device__ __forceinline__ unsigned long long pack2(float v) {
    unsigned long long r;
    asm("mov.b64 %0, {%1, %1};" : "=l"(r) : "f"(v));
    return r;
}
__device__ __forceinline__ void fma2(unsigned long long& d, unsigned long long a,
                                     unsigned long long b) {
    asm("fma.rn.f32x2 %0, %1, %2, %0;" : "+l"(d) : "l"(a), "l"(b));
}

// ---------------------------------------------------------------------------
// Prep (merged, vectorized):
//  blocks [0, QUAD_BLOCKS): build row_ptr from sorted dst_idx, 4 edges/thread
//    via one int4 load (4x MLP, half the index bytes of the scalar version).
//  blocks [QUAD_BLOCKS, +W_BLOCKS): transpose W [64][128] -> g_wt[k][o].
// ---------------------------------------------------------------------------
#define N_QUADS     (N_EDGES / 4)                  // 200000 (N_EDGES % 4 == 0)
#define QUAD_BLOCKS ((N_QUADS + 255) / 256)        // 782
#define W_BLOCKS    ((64 * 128 + 255) / 256)       // 32

__global__ void prep_kernel(const int* __restrict__ dst_idx,
                            const float* __restrict__ W) {
    if (blockIdx.x >= QUAD_BLOCKS) {
        int t = (blockIdx.x - QUAD_BLOCKS) * blockDim.x + threadIdx.x;
        if (t < 64 * 128) {
            int o = t >> 7;          // 0..63
            int k = t & 127;         // 0..127
            g_wt[k * 64 + o] = W[o * 128 + k];
        }
        return;
    }
    int q = blockIdx.x * blockDim.x + threadIdx.x;
    if (q >= N_QUADS) return;
    int e0 = q * 4;
    int4 d4 = ((const int4*)dst_idx)[q];
    int dprev = (e0 == 0) ? -1 : __ldg(&dst_idx[e0 - 1]);

    // gap-fill: row_ptr[x] = first edge with dst >= x
    for (int x = dprev + 1; x <= d4.x; ++x) g_row_ptr[x] = e0;
    for (int x = d4.x + 1; x <= d4.y; ++x) g_row_ptr[x] = e0 + 1;
    for (int x = d4.y + 1; x <= d4.z; ++x) g_row_ptr[x] = e0 + 2;
    for (int x = d4.z + 1; x <= d4.w; ++x) g_row_ptr[x] = e0 + 3;

    if (e0 + 4 == N_EDGES) {
        for (int x = d4.w + 1; x <= N_DST; ++x) g_row_ptr[x] = N_EDGES;
    }
}

// ---------------------------------------------------------------------------
// Kernel B: aggregation + CV blend. Warp per dst row, 8-way unrolled gather.
// No smem -> max occupancy. Writes h_neigh only. (Measured near L2 floor.)
// ---------------------------------------------------------------------------
#define AGG_THREADS 256
#define AGG_ROWS    8

__global__ __launch_bounds__(AGG_THREADS) void aggregate_kernel(
    const float* __restrict__ H_src,
    const float* __restrict__ HBar,
    const int*   __restrict__ src_idx,
    float* __restrict__ out_hn)
{
    const int warp = threadIdx.x >> 5;
    const int lane = threadIdx.x & 31;
    const int row  = blockIdx.x * AGG_ROWS + warp;
    if (row >= N_DST) return;

    const int start = g_row_ptr[row];
    const int end   = g_row_ptr[row + 1];
    const int deg   = end - start;

    const float2* Hs2 = (const float2*)H_src;
    float2 hb = ((const float2*)HBar)[row * 32 + lane];

    float2 sum = make_float2(0.f, 0.f);
    int e = start;
    for (; e + 7 < end; e += 8) {
        int s0 = src_idx[e + 0], s1 = src_idx[e + 1];
        int s2 = src_idx[e + 2], s3 = src_idx[e + 3];
        int s4 = src_idx[e + 4], s5 = src_idx[e + 5];
        int s6 = src_idx[e + 6], s7 = src_idx[e + 7];
        float2 a0 = Hs2[s0 * 32 + lane];
        float2 a1 = Hs2[s1 * 32 + lane];
        float2 a2 = Hs2[s2 * 32 + lane];
        float2 a3 = Hs2[s3 * 32 + lane];
        float2 a4 = Hs2[s4 * 32 + lane];
        float2 a5 = Hs2[s5 * 32 + lane];
        float2 a6 = Hs2[s6 * 32 + lane];
        float2 a7 = Hs2[s7 * 32 + lane];
        sum.x += ((a0.x + a1.x) + (a2.x + a3.x)) + ((a4.x + a5.x) + (a6.x + a7.x));
        sum.y += ((a0.y + a1.y) + (a2.y + a3.y)) + ((a4.y + a5.y) + (a6.y + a7.y));
    }
    for (; e + 1 < end; e += 2) {
        int s0 = src_idx[e + 0], s1 = src_idx[e + 1];
        float2 a0 = Hs2[s0 * 32 + lane];
        float2 a1 = Hs2[s1 * 32 + lane];
        sum.x += a0.x + a1.x;
        sum.y += a0.y + a1.y;
    }
    if (e < end) {
        int s = src_idx[e];
        float2 a = Hs2[s * 32 + lane];
        sum.x += a.x;
        sum.y += a.y;
    }

    float inv = 1.0f / (float)max(deg, 1);
    float2 hn;
    hn.x = 0.9f * hb.x + 0.1f * (sum.x * inv);
    hn.y = 0.9f * hb.y + 0.1f * (sum.y * inv);
    ((float2*)out_hn)[row * 32 + lane] = hn;
}

// ---------------------------------------------------------------------------
// Kernel C: GEMM  h = relu([H_dst | h_neigh] @ W^T + b)
// 64 rows x 64 outs per 128-thread block, full K=128.
// Thread tile: 8 rows x 4 outs. Per k: 2 LDS.128 + 1 LDG.128 (W, L1-hot)
// + 4 packs + 16 fma.rn.f32x2  => 23 inst / 32 FMA.
// X k-major in 32KB smem, swizzle r ^ (k & 56).
// ---------------------------------------------------------------------------
#define G_ROWS    64
#define G_THREADS 128
#define GEMM_BLOCKS ((N_DST + G_ROWS - 1) / G_ROWS)   // 782

__global__ __launch_bounds__(G_THREADS, 6) void gemm_kernel(
    const float* __restrict__ H_dst,
    const float* __restrict__ hn,
    const float* __restrict__ bias,
    float* __restrict__ out_h)
{
    __shared__ float xt[128][64];   // 32KB

    const int tid = threadIdx.x;
    const int rowBase = blockIdx.x * G_ROWS;

    // --- stage X: k<64 from H_dst, k>=64 from hn ---
    for (int i = tid; i < 64 * 16; i += G_THREADS) {
        int r  = i >> 4;
        int c4 = i & 15;
        int row = rowBase + r;
        float4 vd = make_float4(0.f, 0.f, 0.f, 0.f);
        float4 vn = make_float4(0.f, 0.f, 0.f, 0.f);
        if (row < N_DST) {
            vd = ((const float4*)H_dst)[row * 16 + c4];
            vn = ((const float4*)hn)   [row * 16 + c4];
        }
        int k0 = 4 * c4;
        xt[k0 + 0][r ^ ((k0 + 0) & 56)] = vd.x;
        xt[k0 + 1][r ^ ((k0 + 1) & 56)] = vd.y;
        xt[k0 + 2][r ^ ((k0 + 2) & 56)] = vd.z;
        xt[k0 + 3][r ^ ((k0 + 3) & 56)] = vd.w;
        int k1 = 64 + 4 * c4;
        xt[k1 + 0][r ^ ((k1 + 0) & 56)] = vn.x;
        xt[k1 + 1][r ^ ((k1 + 1) & 56)] = vn.y;
        xt[k1 + 2][r ^ ((k1 + 2) & 56)] = vn.z;
        xt[k1 + 3][r ^ ((k1 + 3) & 56)] = vn.w;
    }
    __syncthreads();

    // --- mainloop: 8 rows (4 packed pairs) x 4 outs per thread ---
    const int rg = tid >> 4;    // 0..7  -> rows 8*rg .. 8*rg+7
    const int cg = tid & 15;    // 0..15 -> outs 4*cg .. 4*cg+3

    unsigned long long acc[4][4];
#pragma unroll
    for (int p = 0; p < 4; p++)
#pragma unroll
        for (int j = 0; j < 4; j++) acc[p][j] = 0ULL;

    const float4* wt4 = (const float4*)g_wt;

#pragma unroll 8
    for (int k = 0; k < 128; k++) {
        const int sw = k & 56;
        const int base = (8 * rg) ^ sw;           // 8-aligned
        ulonglong2 xlo = *(const ulonglong2*)&xt[k][base];      // rows 8rg..+3
        ulonglong2 xhi = *(const ulonglong2*)&xt[k][base + 4];  // rows 8rg+4..+7

        float4 wv = __ldg(&wt4[k * 16 + cg]);     // 256B contiguous per warp
        unsigned long long w0 = pack2(wv.x);
        unsigned long long w1 = pack2(wv.y);
        unsigned long long w2 = pack2(wv.z);
        unsigned long long w3 = pack2(wv.w);

        fma2(acc[0][0], xlo.x, w0); fma2(acc[0][1], xlo.x, w1);
        fma2(acc[0][2], xlo.x, w2); fma2(acc[0][3], xlo.x, w3);
        fma2(acc[1][0], xlo.y, w0); fma2(acc[1][1], xlo.y, w1);
        fma2(acc[1][2], xlo.y, w2); fma2(acc[1][3], xlo.y, w3);
        fma2(acc[2][0], xhi.x, w0); fma2(acc[2][1], xhi.x, w1);
        fma2(acc[2][2], xhi.x, w2); fma2(acc[2][3], xhi.x, w3);
        fma2(acc[3][0], xhi.y, w0); fma2(acc[3][1], xhi.y, w1);
        fma2(acc[3][2], xhi.y, w2); fma2(acc[3][3], xhi.y, w3);
    }

    // --- epilogue: bias + relu, float4 stores ---
    float4 bv = __ldg(&((const float4*)bias)[cg]);
#pragma unroll
    for (int p = 0; p < 4; p++) {
        float lo[4], hi[4];
#pragma unroll
        for (int j = 0; j < 4; j++) {
            float l, h;
            asm("mov.b64 {%0, %1}, %2;" : "=f"(l), "=f"(h) : "l"(acc[p][j]));
            lo[j] = l; hi[j] = h;
        }
        int r0 = rowBase + 8 * rg + 2 * p;
        if (r0 < N_DST) {
            float4 v;
            v.x = fmaxf(lo[0] + bv.x, 0.f);
            v.y = fmaxf(lo[1] + bv.y, 0.f);
            v.z = fmaxf(lo[2] + bv.z, 0.f);
            v.w = fmaxf(lo[3] + bv.w, 0.f);
            ((float4*)out_h)[r0 * 16 + cg] = v;
        }
        if (r0 + 1 < N_DST) {
            float4 v;
            v.x = fmaxf(hi[0] + bv.x, 0.f);
            v.y = fmaxf(hi[1] + bv.y, 0.f);
            v.z = fmaxf(hi[2] + bv.z, 0.f);
            v.w = fmaxf(hi[3] + bv.w, 0.f);
            ((float4*)out_h)[(r0 + 1) * 16 + cg] = v;
        }
    }
}

// ---------------------------------------------------------------------------
extern "C" void kernel_launch(void* const* d_in, const int* in_sizes, int n_in,
                              void* d_out, int out_size) {
    const float* H_src   = (const float*)d_in[0];
    const float* H_dst   = (const float*)d_in[1];
    const float* HBar    = (const float*)d_in[2];
    const int*   src_idx = (const int*)  d_in[3];
    const int*   dst_idx = (const int*)  d_in[4];
    const float* W       = (const float*)d_in[5];
    const float* bias    = (const float*)d_in[6];

    float* out_h  = (float*)d_out;                     // [N_DST, 64]
    float* out_hn = (float*)d_out + N_DST * 64;        // [N_DST, 64]

    prep_kernel<<<QUAD_BLOCKS + W_BLOCKS, 256>>>(dst_idx, W);

    aggregate_kernel<<<(N_DST + AGG_ROWS - 1) / AGG_ROWS, AGG_THREADS>>>(
        H_src, HBar, src_idx, out_hn);

    gemm_kernel<<<GEMM_BLOCKS, G_THREADS>>>(H_dst, out_hn, bias, out_h);
}